// round 5
// baseline (speedup 1.0000x reference)
#include <cuda_runtime.h>
#include <cstdint>

#define H_DIM   4096
#define R_DIM   16
#define N_TOK   32768          // B*S
#define TBW     4              // tokens per WARP (kernel1)
#define NW      8              // warps per block
#define TB1     (TBW*NW)       // 32 tokens per block (kernel1)
#define TB2     16             // tokens per block (kernel2)
#define NTHREADS 256
#define KSCALE ((float)(2.0 / 0.95))
#define PDROP  0.05f

__device__ float g_mid[N_TOK * R_DIM];        // 2 MB scratch
__device__ float g_bt[8 * R_DIM * H_DIM];     // 2 MB: Bt[e][r][h]

// ---- packed f32x2 helpers ---------------------------------------------------
__device__ __forceinline__ unsigned long long ffma2(unsigned long long a,
                                                    unsigned long long b,
                                                    unsigned long long c) {
    unsigned long long d;
    asm("fma.rn.f32x2 %0, %1, %2, %3;" : "=l"(d) : "l"(a), "l"(b), "l"(c));
    return d;
}
__device__ __forceinline__ unsigned long long pack2(float lo, float hi) {
    unsigned long long d;
    asm("mov.b64 %0, {%1, %2};" : "=l"(d) : "f"(lo), "f"(hi));
    return d;
}
__device__ __forceinline__ float2 unpack2(unsigned long long v) {
    float lo, hi;
    asm("mov.b64 {%0, %1}, %2;" : "=f"(lo), "=f"(hi) : "l"(v));
    return make_float2(lo, hi);
}

// ---------------------------------------------------------------------------
// Kernel 0: transpose lora_b[e][h][r] -> g_bt[e][r][h]  (~6us, one-shot)
// ---------------------------------------------------------------------------
__global__ void transpose_b_kernel(const float* __restrict__ lora_b)
{
    const int idx = blockIdx.x * blockDim.x + threadIdx.x;   // 524288
    const int r = idx & 15;
    const int h = (idx >> 4) & 4095;
    const int e = idx >> 16;
    g_bt[((size_t)e * R_DIM + r) * H_DIM + h] = lora_b[idx];
}

// ---------------------------------------------------------------------------
// Kernel 1: mid[g][r] = sum_h dropped(g,h) * A[e][r][h]
// 8 warps x 4 tokens = 32 tokens/block. Each warp private: lanes stride h,
// acc[4][16] in regs, butterfly-only reduction, lane 0 writes float4s.
// A rows shared across all 8 warps via L1 (64KB working set per h-step).
// ---------------------------------------------------------------------------
__global__ __launch_bounds__(NTHREADS, 2)
void lora_mid_kernel(const float* __restrict__ data,
                     const float* __restrict__ mask,
                     const float* __restrict__ lora_a)
{
    const int tid  = threadIdx.x;
    const int wid  = tid >> 5;
    const int lane = tid & 31;
    const int gw   = blockIdx.x * TB1 + wid * TBW;   // first token of warp
    const int e    = blockIdx.x >> 7;                // (blockIdx.x*32)/4096
    const float* aBase = lora_a + (size_t)e * (R_DIM * H_DIM);

    float acc[TBW][R_DIM];
#pragma unroll
    for (int t = 0; t < TBW; t++)
#pragma unroll
        for (int r = 0; r < R_DIM; r++) acc[t][r] = 0.f;

#pragma unroll 4
    for (int it = 0; it < H_DIM / (4 * 32); it++) {   // 32 iterations
        const int h4 = (it * 32 + lane) * 4;

        float4 dr[TBW];
#pragma unroll
        for (int t = 0; t < TBW; t++) {
            const size_t off = (size_t)(gw + t) * H_DIM + h4;
            float4 x = __ldcs((const float4*)(data + off));
            float4 m = __ldcs((const float4*)(mask + off));
            dr[t].x = (m.x >= PDROP) ? x.x * KSCALE : 0.f;
            dr[t].y = (m.y >= PDROP) ? x.y * KSCALE : 0.f;
            dr[t].z = (m.z >= PDROP) ? x.z * KSCALE : 0.f;
            dr[t].w = (m.w >= PDROP) ? x.w * KSCALE : 0.f;
        }

#pragma unroll
        for (int r = 0; r < R_DIM; r++) {
            const float4 a4 = *(const float4*)(aBase + r * H_DIM + h4);
#pragma unroll
            for (int t = 0; t < TBW; t++) {
                acc[t][r] += dr[t].x * a4.x + dr[t].y * a4.y
                           + dr[t].z * a4.z + dr[t].w * a4.w;
            }
        }
    }

    // warp-private butterfly reduction over h-lanes
#pragma unroll
    for (int t = 0; t < TBW; t++)
#pragma unroll
        for (int r = 0; r < R_DIM; r++) {
#pragma unroll
            for (int off = 16; off > 0; off >>= 1)
                acc[t][r] += __shfl_xor_sync(0xffffffffu, acc[t][r], off);
        }

    if (lane == 0) {
#pragma unroll
        for (int t = 0; t < TBW; t++) {
            float* mp = g_mid + (size_t)(gw + t) * R_DIM;
            *(float4*)(mp + 0)  = make_float4(acc[t][0],  acc[t][1],  acc[t][2],  acc[t][3]);
            *(float4*)(mp + 4)  = make_float4(acc[t][4],  acc[t][5],  acc[t][6],  acc[t][7]);
            *(float4*)(mp + 8)  = make_float4(acc[t][8],  acc[t][9],  acc[t][10], acc[t][11]);
            *(float4*)(mp + 12) = make_float4(acc[t][12], acc[t][13], acc[t][14], acc[t][15]);
        }
    }
}

// ---------------------------------------------------------------------------
// Kernel 2: out[g][h] = result[g][h] + sum_r mid[g][r] * Bt[e][r][h]
// TB2=16 tokens/block; Bt coalesced float4, reused x16; f32x2 packed FMAs;
// mid in smem as duplicated f32x2 pairs (LDS.64 broadcast).
// grid = (N_TOK/TB2, H/1024)
// ---------------------------------------------------------------------------
__global__ __launch_bounds__(NTHREADS)
void lora_out_kernel(const float* __restrict__ result,
                     float* __restrict__ out)
{
    const int tid = threadIdx.x;
    const int g0  = blockIdx.x * TB2;
    const int e   = g0 >> 12;
    const int h4  = (blockIdx.y * NTHREADS + tid) * 4;
    const float* btBase = g_bt + (size_t)e * (R_DIM * H_DIM);

    __shared__ float2 m2[TB2 * R_DIM];   // duplicated pairs
    if (tid < TB2 * R_DIM) {
        float v = g_mid[(size_t)g0 * R_DIM + tid];
        m2[tid] = make_float2(v, v);
    }
    __syncthreads();
    const unsigned long long* m2u = (const unsigned long long*)m2;

    unsigned long long accl[TB2], acch[TB2];
#pragma unroll
    for (int t = 0; t < TB2; t++) {
        float4 rv = __ldcs((const float4*)(result + (size_t)(g0 + t) * H_DIM + h4));
        accl[t] = pack2(rv.x, rv.y);
        acch[t] = pack2(rv.z, rv.w);
    }

#pragma unroll
    for (int r = 0; r < R_DIM; r++) {
        const float4 b4 = *(const float4*)(btBase + (size_t)r * H_DIM + h4);
        const unsigned long long bl = pack2(b4.x, b4.y);
        const unsigned long long bh = pack2(b4.z, b4.w);
#pragma unroll
        for (int t = 0; t < TB2; t++) {
            const unsigned long long m = m2u[t * R_DIM + r];
            accl[t] = ffma2(m, bl, accl[t]);
            acch[t] = ffma2(m, bh, acch[t]);
        }
    }

#pragma unroll
    for (int t = 0; t < TB2; t++) {
        float2 lo = unpack2(accl[t]);
        float2 hi = unpack2(acch[t]);
        __stcs((float4*)(out + (size_t)(g0 + t) * H_DIM + h4),
               make_float4(lo.x, lo.y, hi.x, hi.y));
    }
}

// ---------------------------------------------------------------------------
extern "C" void kernel_launch(void* const* d_in, const int* in_sizes, int n_in,
                              void* d_out, int out_size)
{
    const float* result   = (const float*)d_in[0];
    const float* data     = (const float*)d_in[1];
    const float* dropmask = (const float*)d_in[2];
    const float* lora_a   = (const float*)d_in[3];
    const float* lora_b   = (const float*)d_in[4];
    float* out = (float*)d_out;

    transpose_b_kernel<<<(8 * R_DIM * H_DIM) / NTHREADS, NTHREADS>>>(lora_b);
    lora_mid_kernel<<<N_TOK / TB1, NTHREADS>>>(data, dropmask, lora_a);

    dim3 grid2(N_TOK / TB2, H_DIM / (4 * NTHREADS));
    lora_out_kernel<<<grid2, NTHREADS>>>(result, out);
}